// round 6
// baseline (speedup 1.0000x reference)
#include <cuda_runtime.h>
#include <cuda_bf16.h>
#include <cstdint>
#include <math.h>

#define BATCH  256
#define SEQ    64
#define DMODEL 512
#define HDIM   512
#define NHEAD  8
#define DK     64
#define EPS_F  1e-7f

#define OUT_ELEMS  (BATCH * SEQ * DMODEL)          // 8388608
#define ATTN_ELEMS (NHEAD * BATCH * SEQ * SEQ)     // 8388608
#define ATTN_OFF   OUT_ELEMS
#define SCALAR_OFF (OUT_ELEMS + ATTN_ELEMS)

// Scratch (device globals; allocation-free per harness rules)
__device__ float g_qh[BATCH * SEQ * HDIM];
__device__ float g_kh[BATCH * SEQ * HDIM];
__device__ float g_vh[BATCH * SEQ * HDIM];
__device__ float g_o [BATCH * SEQ * HDIM];

// ---------------------------------------------------------------------------
// bf16 split helpers: x = hi + lo, both bf16. Packed pairs (k, k+1) in b32.
// ---------------------------------------------------------------------------
__device__ __forceinline__ void bsplit2(float x, float y, uint32_t& h, uint32_t& l) {
    __nv_bfloat16 hx = __float2bfloat16_rn(x);
    __nv_bfloat16 hy = __float2bfloat16_rn(y);
    float rx = x - __bfloat162float(hx);
    float ry = y - __bfloat162float(hy);
    __nv_bfloat16 lx = __float2bfloat16_rn(rx);
    __nv_bfloat16 ly = __float2bfloat16_rn(ry);
    h = (uint32_t)__bfloat16_as_ushort(hx) | ((uint32_t)__bfloat16_as_ushort(hy) << 16);
    l = (uint32_t)__bfloat16_as_ushort(lx) | ((uint32_t)__bfloat16_as_ushort(ly) << 16);
}

// D += A(16x16) * B(16x8), bf16 inputs, fp32 accum (legacy path, plain sm_103)
__device__ __forceinline__ void mma_bf16(float* c, const uint32_t* a, const uint32_t* b) {
    asm volatile(
        "mma.sync.aligned.m16n8k16.row.col.f32.bf16.bf16.f32 "
        "{%0,%1,%2,%3}, {%4,%5,%6,%7}, {%8,%9}, {%0,%1,%2,%3};"
        : "+f"(c[0]), "+f"(c[1]), "+f"(c[2]), "+f"(c[3])
        : "r"(a[0]), "r"(a[1]), "r"(a[2]), "r"(a[3]), "r"(b[0]), "r"(b[1]));
}

#define PA   12    // A/[o][kp] pitch in uint32 (8 kpairs + 4 pad): frag bank 12g+t distinct
#define PBP  136   // proj B [kp][o] pitch: frag bank 8t+g distinct

// ---------------------------------------------------------------------------
// Kernel A: group-linear projections via split-bf16 mma.sync.
//   Per (proj, n): (256 x 512) @ (512 x 512). CTA tile M=128, N=128, BK=16.
//   8 warps as 2x4 (m x n); warp tile 64x32; m16n8k16; 3-MMA split.
//   2-stage smem pipeline: LDG(it+1) || MMA(it), single barrier per iter.
// grid = (2, 4, 192), block = 256
// ---------------------------------------------------------------------------
__global__ __launch_bounds__(256, 2) void proj_mma(
    const float* __restrict__ q, const float* __restrict__ kin, const float* __restrict__ v,
    const float* __restrict__ Wq, const float* __restrict__ Wk, const float* __restrict__ Wv)
{
    __shared__ __align__(16) uint32_t Ahi[2][128 * PA], Alo[2][128 * PA];   // [m][kpair]
    __shared__ __align__(16) uint32_t Bhi[2][8 * PBP],  Blo[2][8 * PBP];    // [kpair][o]

    const int z = blockIdx.z;
    const int proj = z >> 6, n = z & 63;
    const float* X; const float* W; float* Y;
    if (proj == 0)      { X = q;   W = Wq; Y = g_qh; }
    else if (proj == 1) { X = kin; W = Wk; Y = g_kh; }
    else                { X = v;   W = Wv; Y = g_vh; }

    const int m0 = blockIdx.x * 128;
    const int o0 = blockIdx.y * 128;

    const int tid  = threadIdx.x;
    const int lane = tid & 31;
    const int wid  = tid >> 5;
    const int g    = lane >> 2;
    const int t    = lane & 3;
    const int warp_m = (wid & 1) * 64;
    const int warp_n = (wid >> 1) * 32;

    const int ar = tid >> 1, sA = (tid & 1);        // A: row, k-half
    const int kp = tid >> 5, og = lane * 4;         // B: kpair row, o-offset

    const float* abase = X + (size_t)(m0 + ar) * (SEQ * DMODEL) + (size_t)n * DMODEL + sA * 8;
    const float* bbase = W + (size_t)n * (DMODEL * HDIM) + (size_t)(2 * kp) * HDIM + o0 + og;

    uint4 sAH, sAL, sBH, sBL;

    // stage iteration 0
    {
        float4 f0 = *(const float4*)abase;
        float4 f1 = *(const float4*)(abase + 4);
        bsplit2(f0.x, f0.y, sAH.x, sAL.x);
        bsplit2(f0.z, f0.w, sAH.y, sAL.y);
        bsplit2(f1.x, f1.y, sAH.z, sAL.z);
        bsplit2(f1.z, f1.w, sAH.w, sAL.w);
        float4 g0 = *(const float4*)bbase;
        float4 g1 = *(const float4*)(bbase + HDIM);
        bsplit2(g0.x, g1.x, sBH.x, sBL.x);
        bsplit2(g0.y, g1.y, sBH.y, sBL.y);
        bsplit2(g0.z, g1.z, sBH.z, sBL.z);
        bsplit2(g0.w, g1.w, sBH.w, sBL.w);
    }
    *(uint4*)&Ahi[0][ar * PA + sA * 4] = sAH;
    *(uint4*)&Alo[0][ar * PA + sA * 4] = sAL;
    *(uint4*)&Bhi[0][kp * PBP + og]    = sBH;
    *(uint4*)&Blo[0][kp * PBP + og]    = sBL;
    __syncthreads();

    float acc[4][4][4] = {};

    for (int it = 0; it < 32; ++it) {
        const int cur = it & 1;

        if (it < 31) {   // stage it+1 (LDG + convert into regs; latency hidden by MMA)
            const int k0 = (it + 1) * 16;
            float4 f0 = *(const float4*)(abase + k0);
            float4 f1 = *(const float4*)(abase + k0 + 4);
            bsplit2(f0.x, f0.y, sAH.x, sAL.x);
            bsplit2(f0.z, f0.w, sAH.y, sAL.y);
            bsplit2(f1.x, f1.y, sAH.z, sAL.z);
            bsplit2(f1.z, f1.w, sAH.w, sAL.w);
            float4 g0 = *(const float4*)(bbase + (size_t)k0 * HDIM);
            float4 g1 = *(const float4*)(bbase + (size_t)(k0 + 1) * HDIM);
            bsplit2(g0.x, g1.x, sBH.x, sBL.x);
            bsplit2(g0.y, g1.y, sBH.y, sBL.y);
            bsplit2(g0.z, g1.z, sBH.z, sBL.z);
            bsplit2(g0.w, g1.w, sBH.w, sBL.w);
        }

        uint32_t af[4][4], bh[4][2], bx[4][2];
        #pragma unroll
        for (int mi = 0; mi < 4; ++mi) {
            const int rb = warp_m + mi * 16;
            af[mi][0] = Ahi[cur][(rb + g)     * PA + t];
            af[mi][1] = Ahi[cur][(rb + g + 8) * PA + t];
            af[mi][2] = Ahi[cur][(rb + g)     * PA + t + 4];
            af[mi][3] = Ahi[cur][(rb + g + 8) * PA + t + 4];
        }
        #pragma unroll
        for (int ni = 0; ni < 4; ++ni) {
            const int nb = warp_n + ni * 8;
            bh[ni][0] = Bhi[cur][t       * PBP + nb + g];
            bh[ni][1] = Bhi[cur][(t + 4) * PBP + nb + g];
        }
        #pragma unroll
        for (int mi = 0; mi < 4; ++mi)
            #pragma unroll
            for (int ni = 0; ni < 4; ++ni)
                mma_bf16(acc[mi][ni], af[mi], bh[ni]);    // hi*hi

        #pragma unroll
        for (int ni = 0; ni < 4; ++ni) {
            const int nb = warp_n + ni * 8;
            bx[ni][0] = Blo[cur][t       * PBP + nb + g];
            bx[ni][1] = Blo[cur][(t + 4) * PBP + nb + g];
        }
        #pragma unroll
        for (int mi = 0; mi < 4; ++mi)
            #pragma unroll
            for (int ni = 0; ni < 4; ++ni)
                mma_bf16(acc[mi][ni], af[mi], bx[ni]);    // hi*lo

        #pragma unroll
        for (int mi = 0; mi < 4; ++mi) {
            const int rb = warp_m + mi * 16;
            af[mi][0] = Alo[cur][(rb + g)     * PA + t];
            af[mi][1] = Alo[cur][(rb + g + 8) * PA + t];
            af[mi][2] = Alo[cur][(rb + g)     * PA + t + 4];
            af[mi][3] = Alo[cur][(rb + g + 8) * PA + t + 4];
        }
        #pragma unroll
        for (int mi = 0; mi < 4; ++mi)
            #pragma unroll
            for (int ni = 0; ni < 4; ++ni)
                mma_bf16(acc[mi][ni], af[mi], bh[ni]);    // lo*hi

        if (it < 31) {
            const int nxt = 1 - cur;
            *(uint4*)&Ahi[nxt][ar * PA + sA * 4] = sAH;
            *(uint4*)&Alo[nxt][ar * PA + sA * 4] = sAL;
            *(uint4*)&Bhi[nxt][kp * PBP + og]    = sBH;
            *(uint4*)&Blo[nxt][kp * PBP + og]    = sBL;
        }
        __syncthreads();
    }

    #pragma unroll
    for (int mi = 0; mi < 4; ++mi) {
        const int r0 = m0 + warp_m + mi * 16 + g;
        #pragma unroll
        for (int ni = 0; ni < 4; ++ni) {
            const int c0 = o0 + warp_n + ni * 8 + 2 * t;
            *(float2*)(Y + ((size_t)r0 * SEQ + n) * HDIM + c0) =
                make_float2(acc[mi][ni][0], acc[mi][ni][1]);
            *(float2*)(Y + ((size_t)(r0 + 8) * SEQ + n) * HDIM + c0) =
                make_float2(acc[mi][ni][2], acc[mi][ni][3]);
        }
    }
}

// ---------------------------------------------------------------------------
// Kernel B: attention per (b, h) — SIMT (small GEMMs + softmax/top-5)
// ---------------------------------------------------------------------------
__global__ __launch_bounds__(256) void attn_kernel(float* __restrict__ d_out, int write_attn)
{
    __shared__ float qs[SEQ * 64];
    __shared__ float ks[SEQ * 64];
    __shared__ float sc[SEQ * 64];

    const int bh = blockIdx.x;
    const int b  = bh >> 3;
    const int h  = bh & 7;

    const int tid  = threadIdx.x;
    const int lane = tid & 31;
    const int warp = tid >> 5;
    const int tx   = tid & 15;
    const int ty   = tid >> 4;

    const float* qb = g_qh + (size_t)b * SEQ * HDIM + (size_t)h * DK;
    const float* kb = g_kh + (size_t)b * SEQ * HDIM + (size_t)h * DK;
    const float* vb = g_vh + (size_t)b * SEQ * HDIM + (size_t)h * DK;

    for (int i = tid; i < 1024; i += 256) {
        int r = i >> 4, c = (i & 15) * 4;
        *reinterpret_cast<float4*>(&qs[r * 64 + c]) =
            *reinterpret_cast<const float4*>(qb + (size_t)r * HDIM + c);
    }
    for (int i = tid; i < 1024; i += 256) {
        int r = i & 63, c = (i >> 6) * 4;
        float4 kv = *reinterpret_cast<const float4*>(kb + (size_t)r * HDIM + c);
        ks[(c + 0) * 64 + r] = kv.x;
        ks[(c + 1) * 64 + r] = kv.y;
        ks[(c + 2) * 64 + r] = kv.z;
        ks[(c + 3) * 64 + r] = kv.w;
    }
    __syncthreads();

    {
        float acc[4][4] = {};
        #pragma unroll 4
        for (int d = 0; d < 64; d++) {
            float4 bb = *reinterpret_cast<const float4*>(&ks[d * 64 + tx * 4]);
            #pragma unroll
            for (int ii = 0; ii < 4; ii++) {
                float a = qs[(ty * 4 + ii) * 64 + d];
                acc[ii][0] += a * bb.x;
                acc[ii][1] += a * bb.y;
                acc[ii][2] += a * bb.z;
                acc[ii][3] += a * bb.w;
            }
        }
        #pragma unroll
        for (int ii = 0; ii < 4; ii++)
            #pragma unroll
            for (int jj = 0; jj < 4; jj++)
                sc[(ty * 4 + ii) * 64 + tx * 4 + jj] = acc[ii][jj] * 0.125f;
    }
    __syncthreads();

    for (int i = tid; i < 1024; i += 256) {
        int r = i >> 4, c = (i & 15) * 4;
        *reinterpret_cast<float4*>(&qs[r * 64 + c]) =
            *reinterpret_cast<const float4*>(vb + (size_t)r * HDIM + c);
    }

    const unsigned FULL = 0xffffffffu;
    for (int rr = 0; rr < 8; rr++) {
        int r = warp * 8 + rr;
        float s0 = sc[r * 64 + lane];
        float s1 = sc[r * 64 + 32 + lane];

        float m = fmaxf(s0, s1);
        #pragma unroll
        for (int off = 16; off; off >>= 1) m = fmaxf(m, __shfl_xor_sync(FULL, m, off));
        float e0 = expf(s0 - m), e1 = expf(s1 - m);
        float s = e0 + e1;
        #pragma unroll
        for (int off = 16; off; off >>= 1) s += __shfl_xor_sync(FULL, s, off);
        float p0 = e0 / s, p1 = e1 / s;

        float a = p0, c = p1, kth = 0.0f;
        #pragma unroll
        for (int tI = 0; tI < 5; tI++) {
            float mm = fmaxf(a, c);
            #pragma unroll
            for (int off = 16; off; off >>= 1) mm = fmaxf(mm, __shfl_xor_sync(FULL, mm, off));
            kth = mm;
            unsigned ba = __ballot_sync(FULL, a == mm);
            unsigned bc = __ballot_sync(FULL, c == mm);
            if (ba) { if (lane == __ffs(ba) - 1) a = -1e30f; }
            else    { if (lane == __ffs(bc) - 1) c = -1e30f; }
        }

        float delta = kth + EPS_F;
        float w0 = fmaxf(p0 - delta, 0.0f);
        float w1 = fmaxf(p1 - delta, 0.0f);
        float ws = w0 + w1;
        #pragma unroll
        for (int off = 16; off; off >>= 1) ws += __shfl_xor_sync(FULL, ws, off);
        float denom = ws + EPS_F;
        w0 /= denom;
        w1 /= denom;

        sc[r * 64 + lane]      = w0;
        sc[r * 64 + 32 + lane] = w1;
        if (write_attn) {
            size_t ab = (size_t)ATTN_OFF + (((size_t)(h * BATCH + b) * 64 + r) * 64);
            d_out[ab + lane]      = w0;
            d_out[ab + 32 + lane] = w1;
        }
    }
    __syncthreads();

    {
        float acc[4][4] = {};
        #pragma unroll 4
        for (int j = 0; j < 64; j++) {
            float4 bb = *reinterpret_cast<const float4*>(&qs[j * 64 + tx * 4]);
            #pragma unroll
            for (int ii = 0; ii < 4; ii++) {
                float p = sc[(ty * 4 + ii) * 64 + j];
                acc[ii][0] += p * bb.x;
                acc[ii][1] += p * bb.y;
                acc[ii][2] += p * bb.z;
                acc[ii][3] += p * bb.w;
            }
        }
        #pragma unroll
        for (int ii = 0; ii < 4; ii++) {
            int qq = ty * 4 + ii;
            float4 r = make_float4(acc[ii][0], acc[ii][1], acc[ii][2], acc[ii][3]);
            *reinterpret_cast<float4*>(g_o + ((size_t)b * SEQ + qq) * HDIM + (size_t)h * DK + tx * 4) = r;
        }
    }
}

// ---------------------------------------------------------------------------
// Kernel C: fc + gate via split-bf16 mma.sync, fused gated-tanh epilogue.
//   CTA tile M=128, N=64, BK=16; 2-stage smem pipeline (dynamic smem 48KB).
// grid = (128, 8), block = 256
// ---------------------------------------------------------------------------
#define OA_HI(buf)  (dsm + (buf) * 6144 + 0)
#define OA_LO(buf)  (dsm + (buf) * 6144 + 1536)
#define OB_FH(buf)  (dsm + (buf) * 6144 + 3072)
#define OB_FL(buf)  (dsm + (buf) * 6144 + 3840)
#define OB_GH(buf)  (dsm + (buf) * 6144 + 4608)
#define OB_GL(buf)  (dsm + (buf) * 6144 + 5376)

__global__ __launch_bounds__(256, 2) void out_mma(
    const float* __restrict__ fc_w, const float* __restrict__ fc_b,
    const float* __restrict__ gw,   const float* __restrict__ gb,
    float* __restrict__ d_out, int write_scalar)
{
    extern __shared__ __align__(16) uint32_t dsm[];   // 2 bufs x 6144 u32 = 48KB
    __shared__ float sbf[64], sbg[64];

    const int m0 = blockIdx.x * 128;
    const int o0 = blockIdx.y * 64;

    const int tid  = threadIdx.x;
    const int lane = tid & 31;
    const int wid  = tid >> 5;
    const int g    = lane >> 2;
    const int t    = lane & 3;
    const int warp_m = (wid & 1) * 64;
    const int warp_n = (wid >> 1) * 16;

    const int ar = tid >> 1, sA = tid & 1;          // A loader
    const int bsel = tid >> 7;                      // 0 -> fc, 1 -> gate
    const int bidx = tid & 127;
    const int br = bidx >> 1, sB = bidx & 1;        // B loader: o-row, k-half

    if (tid < 64) { sbf[tid] = fc_b[o0 + tid]; sbg[tid] = gb[o0 + tid]; }

    const float* abase = g_o + (size_t)(m0 + ar) * HDIM + sA * 8;
    const float* wbase = (bsel ? gw : fc_w) + (size_t)(o0 + br) * HDIM + sB * 8;
    uint32_t* BH0 = bsel ? OB_GH(0) : OB_FH(0);
    uint32_t* BL0 = bsel ? OB_GL(0) : OB_FL(0);
    uint32_t* BH1 = bsel ? OB_GH(1) : OB_FH(1);
    uint32_t* BL1 = bsel ? OB_GL(1) : OB_FL(1);

    uint4 sAH, sAL, sBH, sBL;

    {   // stage it=0
        float4 f0 = *(const float4*)abase;
        float4 f1 = *(const float4*)(abase + 4);
        bsplit2(f0.x, f0.y, sAH.x, sAL.x);
        bsplit2(f0.z, f0.w, sAH.y, sAL.y);
        bsplit2(f1.x, f1.y, sAH.z, sAL.z);
        bsplit2(f1.z, f1.w, sAH.w, sAL.w);
        float4 w0 = *(const float4*)wbase;
        float4 w1 = *(const float4*)(wbase + 4);
        bsplit2(w0.x, w0.y, sBH.x, sBL.x);
        bsplit2(w0.z, w0.w, sBH.y, sBL.y);
        bsplit2(w1.x, w1.y, sBH.z, sBL.z);
        bsplit2(w1.z, w1.w, sBH.w, sBL.w);
    }
    *(uint4*)&OA_HI(0)[ar * PA + sA * 4] = sAH;
    *(uint4*)&OA_LO(0)[ar * PA + sA * 4] = sAL;
    *(uint4*)&BH0[br * PA + sB * 4] = sBH;
    *(uint4*)&BL0[br * PA + sB * 4] = sBL;
    __syncthreads();

    float accf[4][2][4] = {};
    float accg[4][2][4] = {};

    for (int it = 0; it < 32; ++it) {
        const int cur = it & 1;
        uint32_t* cAhi = OA_HI(cur); uint32_t* cAlo = OA_LO(cur);
        uint32_t* cBfh = OB_FH(cur); uint32_t* cBfl = OB_FL(cur);
        uint32_t* cBgh = OB_GH(cur); uint32_t* cBgl = OB_GL(cur);

        if (it < 31) {
            const int k0 = (it + 1) * 16;
            float4 f0 = *(const float4*)(abase + k0);
            float4 f1 = *(const float4*)(abase + k0 + 4);
            bsplit2(f0.x, f0.y, sAH.x, sAL.x);
            bsplit2(f0.z, f0.w, sAH.y, sAL.y);
            bsplit2(f1.x, f1.y, sAH.z, sAL.z);
            bsplit2(f1.z, f1.w, sAH.w, sAL.w);
            float4 w0 = *(const float4*)(wbase + k0);
            float4 w1 = *(const float4*)(wbase + k0 + 4);
            bsplit2(w0.x, w0.y, sBH.x, sBL.x);
            bsplit2(w0.z, w0.w, sBH.y, sBL.y);
            bsplit2(w1.x, w1.y, sBH.z, sBL.z);
            bsplit2(w1.z, w1.w, sBH.w, sBL.w);
        }

        uint32_t af[4][4], bfh[2][2], bgh[2][2], bq[2][2], bp[2][2];
        #pragma unroll
        for (int mi = 0; mi < 4; ++mi) {
            const int rb = warp_m + mi * 16;
            af[mi][0] = cAhi[(rb + g)     * PA + t];
            af[mi][1] = cAhi[(rb + g + 8) * PA + t];
            af[mi][2] = cAhi[(rb + g)     * PA + t + 4];
            af[mi][3] = cAhi[(rb + g + 8) * PA + t + 4];
        }
        #pragma unroll
        for (int ni = 0; ni < 2; ++ni) {
            const int nb = warp_n + ni * 8;
            bfh[ni][0] = cBfh[(nb + g) * PA + t];
            bfh[ni][1] = cBfh[(nb + g) * PA + t + 4];
            bgh[ni][0] = cBgh[(nb + g) * PA + t];
            bgh[ni][1] = cBgh[(nb + g) * PA + t + 4];
        }
        #pragma unroll
        for (int mi = 0; mi < 4; ++mi)
            #pragma unroll
            for (int ni = 0; ni < 2; ++ni) {
                mma_bf16(accf[mi][ni], af[mi], bfh[ni]);   // hi*hi
                mma_bf16(accg[mi][ni], af[mi], bgh[ni]);
            }

        #pragma unroll
        for (int ni = 0; ni < 2; ++ni) {
            const int nb = warp_n + ni * 8;
            bq[ni][0] = cBfl[(nb + g) * PA + t];
            bq[ni][1] = cBfl[(nb + g) * PA + t + 4];
            bp[ni][0] = cBgl[(nb + g) * PA + t];
            bp[ni][1] = cBgl[(nb + g) * PA + t + 4];
        }
        #pragma unroll
        for (int mi = 0; mi < 4; ++mi)
            #pragma unroll
            for (int ni = 0; ni < 2; ++ni) {
                mma_bf16(accf[mi][ni], af[mi], bq[ni]);    // hi*lo
                mma_bf16(accg[mi][ni], af[mi], bp[ni]);
            }

        #pragma unroll
        for (int mi = 0; mi < 4; ++mi) {
            const int rb = warp_m + mi * 16;
            af[mi][0] = cAlo[(rb + g)     * PA + t];
            af[mi][1] = cAlo[(rb + g + 8) * PA + t];
            af[mi][2] = cAlo[(rb + g)     * PA + t + 4];
            af[mi][3] = cAlo[(rb + g + 8) * PA + t + 4];
        }
        #pragma unroll
        for (int mi = 0; mi < 4; ++mi)
            #pragma unroll
            for (int ni = 0; ni < 2; ++ni) {
                mma_bf16(accf[mi][ni], af[mi], bfh[ni]);   // lo*hi
                mma_bf16(accg[mi][ni], af[mi], bgh[ni]);
            }

        if (it < 31) {
            const int nxt = 1 - cur;
            *(uint4*)&OA_HI(nxt)[ar * PA + sA * 4] = sAH;
            *(uint4*)&OA_LO(nxt)[ar * PA + sA * 4] = sAL;
            uint32_t* dBH = nxt ? BH1 : BH0;
            uint32_t* dBL = nxt ? BL1 : BL0;
            *(uint4*)&dBH[br * PA + sB * 4] = sBH;
            *(uint4*)&dBL[br * PA + sB * 4] = sBL;
        }
        __syncthreads();
    }

    #pragma unroll
    for (int mi = 0; mi < 4; ++mi) {
        const int r0 = m0 + warp_m + mi * 16 + g;
        #pragma unroll
        for (int ni = 0; ni < 2; ++ni) {
            const int lc = warp_n + ni * 8 + 2 * t;
            const int c0 = o0 + lc;
            #pragma unroll
            for (int half = 0; half < 2; ++half) {
                const int row = r0 + half * 8;
                float f0 = accf[mi][ni][half * 2 + 0] + sbf[lc];
                float f1 = accf[mi][ni][half * 2 + 1] + sbf[lc + 1];
                float g0 = accg[mi][ni][half * 2 + 0] + sbg[lc];
                float g1 = accg[mi][ni][half * 2 + 1] + sbg[lc + 1];
                float s0 = 1.0f / (1.0f + expf(-g0));
                float s1 = 1.0f / (1.0f + expf(-g1));
                *(float2*)(d_out + (size_t)row * DMODEL + c0) =
                    make_float2(s0 * tanhf(f0), s1 * tanhf(f1));
            }
        }
    }

    if (write_scalar && blockIdx.x == 0 && blockIdx.y == 0 && tid == 0)
        d_out[SCALAR_OFF] = 0.0f;
}

// ---------------------------------------------------------------------------
extern "C" void kernel_launch(void* const* d_in, const int* in_sizes, int n_in,
                              void* d_out, int out_size)
{
    const float* q      = (const float*)d_in[0];
    const float* k      = (const float*)d_in[1];
    const float* v      = (const float*)d_in[2];
    const float* Wq     = (const float*)d_in[3];
    const float* Wk     = (const float*)d_in[4];
    const float* Wv     = (const float*)d_in[5];
    const float* fc_w   = (const float*)d_in[6];
    const float* fc_b   = (const float*)d_in[7];
    const float* gate_w = (const float*)d_in[8];
    const float* gate_b = (const float*)d_in[9];
    float* out = (float*)d_out;

    const int write_attn   = (out_size >= ATTN_OFF + ATTN_ELEMS) ? 1 : 0;
    const int write_scalar = (out_size >= SCALAR_OFF + 1) ? 1 : 0;

    const int OUT_SMEM = 2 * 6144 * 4;   // 49152 B
    static int configured = 0;
    if (!configured) {
        cudaFuncSetAttribute(out_mma, cudaFuncAttributeMaxDynamicSharedMemorySize, OUT_SMEM);
        configured = 1;
    }

    dim3 gA(2, 4, 192);
    proj_mma<<<gA, 256>>>(q, k, v, Wq, Wk, Wv);

    attn_kernel<<<2048, 256>>>(out, write_attn);

    dim3 gC(128, 8);
    out_mma<<<gC, 256, OUT_SMEM>>>(fc_w, fc_b, gate_w, gate_b, out, write_scalar);
}